// round 8
// baseline (speedup 1.0000x reference)
#include <cuda_runtime.h>
#include <cuda_bf16.h>
#include <math.h>

// pred/target: (32, 3, 512, 512) fp32 -> scalar fp32 mean |sobel(gray(p)) - sobel(gray(t))|
#define B      32
#define H      512
#define W      512
#define PLANE  (H * W)
#define IMG    (3 * PLANE)
#define NPIX   (B * PLANE)            // 8388608

#define RT     32                     // rows per CTA tile
#define TILESY (H / RT)               // 16
#define NBLK   (B * TILESY)           // 512
#define TPB    256                    // 8 warps; warp w owns cols [64w, 64w+64)
// Ring slot layout (floats): [0]=pad  [1]=halo_l  [2..65]=data  [66]=halo_r  [67]=pad
#define WSLOT  68

__device__ float        g_partials[NBLK];
__device__ unsigned int g_count = 0;

__device__ __forceinline__ float fsqrt_approx(float x) {
    float r; asm("sqrt.approx.f32 %0, %1;" : "=f"(r) : "f"(x)); return r;
}

// Prefetch state: one row's rgb (float2 per channel per image) + this lane's edge rgb.
struct Pref {
    float2 r0, g0, b0;   // pred
    float2 r1, g1, b1;   // target
    float  er, eg, eb;   // edge pixel rgb (edge-role lanes only)
};

__device__ __forceinline__ void ldrow(Pref& P,
    const float* __restrict__ pr, const float* __restrict__ tr,
    int gy, int gx, bool isE, const float* __restrict__ ep, int ecol, bool evalid)
{
    if ((unsigned)gy < (unsigned)H) {
        const int o = gy * W + gx;
        P.r0 = *(const float2*)(pr + o);
        P.g0 = *(const float2*)(pr + o + PLANE);
        P.b0 = *(const float2*)(pr + o + 2 * PLANE);
        P.r1 = *(const float2*)(tr + o);
        P.g1 = *(const float2*)(tr + o + PLANE);
        P.b1 = *(const float2*)(tr + o + 2 * PLANE);
        if (isE) {
            if (evalid) {
                const int eo = gy * W + ecol;
                P.er = ep[eo]; P.eg = ep[eo + PLANE]; P.eb = ep[eo + 2 * PLANE];
            } else { P.er = P.eg = P.eb = 0.f; }
        }
    } else {
        P.r0 = P.g0 = P.b0 = make_float2(0.f, 0.f);
        P.r1 = P.g1 = P.b1 = make_float2(0.f, 0.f);
        P.er = P.eg = P.eb = 0.f;
    }
}

// Convert prefetched rgb -> gray and store into this warp's ring slot (both images).
// Data float2 at base + 2 + 2*lane: even float offset -> 8B aligned.
__device__ __forceinline__ void strow(const Pref& P, float* __restrict__ s0,
                                      float* __restrict__ s1, int lane,
                                      bool isE, int eimg, int eoffs)
{
    float2 gp, gt;
    gp.x = 0.299f * P.r0.x + 0.587f * P.g0.x + 0.114f * P.b0.x;
    gp.y = 0.299f * P.r0.y + 0.587f * P.g0.y + 0.114f * P.b0.y;
    gt.x = 0.299f * P.r1.x + 0.587f * P.g1.x + 0.114f * P.b1.x;
    gt.y = 0.299f * P.r1.y + 0.587f * P.g1.y + 0.114f * P.b1.y;
    *(float2*)(s0 + 2 + 2 * lane) = gp;
    *(float2*)(s1 + 2 + 2 * lane) = gt;
    if (isE) {
        float eg = 0.299f * P.er + 0.587f * P.eg + 0.114f * P.eb;
        (eimg ? s1 : s0)[eoffs] = eg;
    }
}

// Horizontal separable partials for local column i (data at slot index i+2).
__device__ __forceinline__ void rdwin(const float* __restrict__ base, int i,
                                      float& hx, float& hs)
{
    float l = base[i + 1], m = base[i + 2], rr = base[i + 3];
    hx = rr - l;                 // [-1, 0, 1]
    hs = l + 2.f * m + rr;       // [ 1, 2, 1]
}

__global__ __launch_bounds__(TPB, 4) void edge_loss_fused(
    const float* __restrict__ pred, const float* __restrict__ tgt,
    float* __restrict__ out)
{
    // Per-warp private rings: [warp][img][slot][WSLOT]  (8.7 KB)
    __shared__ float ring[8 * 2 * 2 * WSLOT];

    const int tid  = threadIdx.x;
    const int w    = tid >> 5;
    const int lane = tid & 31;
    const int tile = blockIdx.x;
    const int b    = blockIdx.y;
    const int gy0  = tile * RT;

    const float* pr = pred + (size_t)b * IMG;
    const float* tr = tgt  + (size_t)b * IMG;

    const int gx = 64 * w + 2 * lane;          // staging cols (2 per lane, both images)

    // Edge roles: lanes 0/1 = left halo (img0/img1), lanes 30/31 = right halo.
    const bool isE    = (lane < 2) || (lane >= 30);
    const int  eimg   = lane & 1;
    const bool eleft  = (lane < 2);
    const int  ecol   = eleft ? (64 * w - 1) : (64 * w + 64);
    const bool evalid = eleft ? (w > 0) : (w < 7);
    const float* ep   = eimg ? tr : pr;
    const int  eoffs  = eleft ? 1 : 66;

    // Ring slot pointers for this warp: [img][slot]
    float* b00 = ring + (w * 4 + 0) * WSLOT;   // img0 slot0
    float* b01 = ring + (w * 4 + 1) * WSLOT;   // img0 slot1
    float* b10 = ring + (w * 4 + 2) * WSLOT;   // img1 slot0
    float* b11 = ring + (w * 4 + 3) * WSLOT;   // img1 slot1

    // ---- Prologue: rows gy0-1 -> slot1, gy0 -> slot0, prefetch gy0+1 ----
    Pref P;
    ldrow(P, pr, tr, gy0 - 1, gx, isE, ep, ecol, evalid);
    strow(P, b01, b11, lane, isE, eimg, eoffs);
    ldrow(P, pr, tr, gy0, gx, isE, ep, ecol, evalid);
    strow(P, b00, b10, lane, isE, eimg, eoffs);
    ldrow(P, pr, tr, gy0 + 1, gx, isE, ep, ecol, evalid);
    __syncwarp();

    // ---- Init rolling windows. Combos j: img = j>>1, local col = (j&1)? 2*lane+1 : 2*lane ----
    float hx0[4], hx1[4], hs0[4], hs1[4];
    {
        const float* s1p[2] = { b01, b11 };    // row -1
        const float* s0p[2] = { b00, b10 };    // row  0
        #pragma unroll
        for (int j = 0; j < 4; j++) {
            const int im = j >> 1;
            const int i  = 2 * lane + (j & 1);
            rdwin(s1p[im], i, hx0[j], hs0[j]);
            rdwin(s0p[im], i, hx1[j], hs1[j]);
        }
    }
    __syncwarp();   // reads of slot1 done before iter 0 overwrites it

    // ---- Warp-autonomous mainloop: STS(r+1) -> LDG(r+2) -> syncwarp -> compute(r) ----
    float acc = 0.f;
    #pragma unroll 2
    for (int r = 0; r < RT; r++) {
        const int s = (r + 1) & 1;
        float* d0 = s ? b01 : b00;
        float* d1 = s ? b11 : b10;
        strow(P, d0, d1, lane, isE, eimg, eoffs);
        if (r < RT - 1)
            ldrow(P, pr, tr, gy0 + r + 2, gx, isE, ep, ecol, evalid);
        __syncwarp();

        float mag[4];
        #pragma unroll
        for (int j = 0; j < 4; j++) {
            const float* bp = (j >> 1) ? d1 : d0;
            const int i  = 2 * lane + (j & 1);
            float hx2, hs2;
            rdwin(bp, i, hx2, hs2);
            float ex = hx0[j] + 2.f * hx1[j] + hx2;
            float ey = hs2 - hs0[j];
            mag[j] = fsqrt_approx(ex * ex + ey * ey);
            hx0[j] = hx1[j]; hx1[j] = hx2;
            hs0[j] = hs1[j]; hs1[j] = hs2;
        }
        acc += fabsf(mag[0] - mag[2]) + fabsf(mag[1] - mag[3]);
    }

    // ---- Block reduction (fixed order) ----
    #pragma unroll
    for (int off = 16; off > 0; off >>= 1)
        acc += __shfl_down_sync(0xffffffffu, acc, off);

    __shared__ float wsum[8];
    __shared__ bool  isLast;
    if (lane == 0) wsum[w] = acc;
    __syncthreads();
    if (tid < 8) {
        float v = wsum[tid];
        #pragma unroll
        for (int off = 4; off > 0; off >>= 1)
            v += __shfl_down_sync(0x000000ffu, v, off);
        if (tid == 0) {
            g_partials[b * TILESY + tile] = v;
            __threadfence();
            unsigned int old = atomicAdd(&g_count, 1u);
            isLast = (old == (unsigned)(NBLK - 1));
        }
    }
    __syncthreads();

    // ---- Fused deterministic final reduction (last block, fp64 fixed order) ----
    if (isLast) {
        __shared__ double ds[TPB];
        double a = 0.0;
        #pragma unroll
        for (int i = 0; i < NBLK / TPB; i++)
            a += (double)__ldcg(&g_partials[tid + i * TPB]);
        ds[tid] = a;
        __syncthreads();
        #pragma unroll
        for (int st = TPB / 2; st > 0; st >>= 1) {
            if (tid < st) ds[tid] += ds[tid + st];
            __syncthreads();
        }
        if (tid == 0) {
            out[0] = (float)(ds[0] / (double)NPIX);
            g_count = 0;   // self-reset for graph replay
        }
    }
}

extern "C" void kernel_launch(void* const* d_in, const int* in_sizes, int n_in,
                              void* d_out, int out_size)
{
    const float* pred = (const float*)d_in[0];
    const float* tgt  = (const float*)d_in[1];
    float* out = (float*)d_out;

    dim3 grid(TILESY, B);   // (16, 32) = 512 blocks
    edge_loss_fused<<<grid, TPB>>>(pred, tgt, out);
}